// round 12
// baseline (speedup 1.0000x reference)
#include <cuda_runtime.h>
#include <cstdint>
#include <math.h>

#define N 4096
#define IN_F 256
#define HH 4
#define OF 128
#define HOF 512
#define SLOPE 0.2f

// Scratch (device globals: no allocations allowed)
__device__ float g_h[N * HOF];           // 8 MB   [n][h*128+f]  (fp32)
__device__ float g_hT[HH * OF * N];      // 8 MB   [h][f][j-permuted] (tf32-rounded)
__device__ float g_ci[N * HH];
__device__ float g_cj[N * HH];

__device__ __forceinline__ uint32_t smem_u32(const void* p) {
    uint32_t a;
    asm("{ .reg .u64 t; cvta.to.shared.u64 t, %1; cvt.u32.u64 %0, t; }" : "=r"(a) : "l"(p));
    return a;
}
__device__ __forceinline__ float to_tf32(float x) {
    float r;
    asm("cvt.rna.tf32.f32 %0, %1;" : "=f"(r) : "f"(x));
    return r;
}
#define CP_ASYNC16(dst_u32, src_ptr) \
    asm volatile("cp.async.cg.shared.global [%0], [%1], 16;" :: "r"(dst_u32), \
                 "l"(__cvta_generic_to_global(src_ptr)))
#define CP_COMMIT() asm volatile("cp.async.commit_group;" ::: "memory")
#define CP_WAIT1()  asm volatile("cp.async.wait_group 1;" ::: "memory")
#define BAR_SYNC(id)   asm volatile("bar.sync %0, 256;" :: "r"(id) : "memory")
#define BAR_ARRIVE(id) asm volatile("bar.arrive %0, 256;" :: "r"(id) : "memory")

// m16n8k8 tf32 MMA, D += A*B (row.col)
__device__ __forceinline__ void mma_tf32(float* c, const uint32_t* a, const uint32_t* b) {
    asm volatile(
        "mma.sync.aligned.m16n8k8.row.col.f32.tf32.tf32.f32 "
        "{%0,%1,%2,%3}, {%4,%5,%6,%7}, {%8,%9}, {%0,%1,%2,%3};"
        : "+f"(c[0]), "+f"(c[1]), "+f"(c[2]), "+f"(c[3])
        : "r"(a[0]), "r"(a[1]), "r"(a[2]), "r"(a[3]), "r"(b[0]), "r"(b[1]));
}

// k-pair interleave inside each 8-group: w -> 2*(w&3) + (w>>2); inverse below
__device__ __forceinline__ int kperm(int w) { return ((w & 3) << 1) | ((w >> 2) & 1); }
__device__ __forceinline__ int kperm_inv(int v) { return ((v & 7) >> 1) | ((v & 1) << 2); }

// ---------------------------------------------------------------------------
// Kernel A (tf32 mma, cp.async 2-stage): g_h = x @ W ; g_hT = tf32 transpose.
// BM=64, BN=64, BK=32; 8 warps 2(M)x4(N); warp tile 32x16.
// Raw fp32 staged (no scatter); cvt to tf32 in registers post-LDS.
// ---------------------------------------------------------------------------
#define XS_STRIDE 40
#define WS_STRIDE 72
#define XS_STAGE (64 * XS_STRIDE)      // 2560
#define WS_STAGE (32 * WS_STRIDE)      // 2304
#define TSW 65
__global__ __launch_bounds__(256) void k_gemm_h(const float* __restrict__ X,
                                                const float* __restrict__ W) {
    __shared__ float SM[2 * XS_STAGE + 2 * WS_STAGE];   // 9728 fl; reused as TS 64x65
    const uint32_t sb = smem_u32(SM);
    const int tid = threadIdx.x;
    const int wid = tid >> 5;
    const int lane = tid & 31;
    const int g = lane >> 2;
    const int t = lane & 3;
    const int row0 = blockIdx.y * 64;
    const int col0 = blockIdx.x * 64;
    const int mrow0 = (wid & 1) * 32;
    const int ncol0 = (wid >> 1) * 16;

    // stage issue helper indices
    const int xm = tid >> 3, xq = tid & 7;           // X: 2 f4/thread via +256
    const int wk = tid >> 4, wn4 = tid & 15;         // W: 2 f4/thread via +256

    // prologue: stage 0 (k0 = 0)
    {
        const uint32_t xd = sb;
        const uint32_t wd = sb + 2 * XS_STAGE * 4;
#pragma unroll
        for (int it = 0; it < 2; it++) {
            int m = xm + 32 * it;
            CP_ASYNC16(xd + (uint32_t)(m * XS_STRIDE + xq * 4) * 4,
                       X + (size_t)(row0 + m) * IN_F + xq * 4);
            int k = wk + 16 * it;
            CP_ASYNC16(wd + (uint32_t)(k * WS_STRIDE + wn4 * 4) * 4,
                       W + (size_t)k * HOF + col0 + wn4 * 4);
        }
        CP_COMMIT();
    }

    float acc[2][2][4];
#pragma unroll
    for (int a = 0; a < 2; a++)
#pragma unroll
        for (int b = 0; b < 2; b++)
#pragma unroll
            for (int c = 0; c < 4; c++) acc[a][b][c] = 0.0f;

    for (int kk = 0; kk < 8; kk++) {
        const int s = kk & 1;
        // issue stage kk+1 (its buffer was last read by mma(kk-1), closed by
        // the barrier at the end of iteration kk-1)
        if (kk + 1 < 8) {
            const int k0 = (kk + 1) * 32;
            const uint32_t xd = sb + (uint32_t)(((kk + 1) & 1) * XS_STAGE) * 4;
            const uint32_t wd = sb + (uint32_t)(2 * XS_STAGE + ((kk + 1) & 1) * WS_STAGE) * 4;
#pragma unroll
            for (int it = 0; it < 2; it++) {
                int m = xm + 32 * it;
                CP_ASYNC16(xd + (uint32_t)(m * XS_STRIDE + xq * 4) * 4,
                           X + (size_t)(row0 + m) * IN_F + k0 + xq * 4);
                int k = wk + 16 * it;
                CP_ASYNC16(wd + (uint32_t)(k * WS_STRIDE + wn4 * 4) * 4,
                           W + (size_t)(k0 + k) * HOF + col0 + wn4 * 4);
            }
        }
        CP_COMMIT();
        CP_WAIT1();       // stage kk complete
        __syncthreads();

        const float* XS = SM + s * XS_STAGE;
        const float* WS = SM + 2 * XS_STAGE + s * WS_STAGE;
#pragma unroll
        for (int ks = 0; ks < 4; ks++) {
            const int kb = ks * 8;
            uint32_t bfr[2][2];
#pragma unroll
            for (int nt = 0; nt < 2; nt++) {
                int n = ncol0 + nt * 8 + g;
                bfr[nt][0] = __float_as_uint(to_tf32(WS[(kb + t) * WS_STRIDE + n]));
                bfr[nt][1] = __float_as_uint(to_tf32(WS[(kb + t + 4) * WS_STRIDE + n]));
            }
#pragma unroll
            for (int mt = 0; mt < 2; mt++) {
                int r0 = mrow0 + mt * 16;
                uint32_t afr[4];
                afr[0] = __float_as_uint(to_tf32(XS[(r0 + g) * XS_STRIDE + kb + t]));
                afr[1] = __float_as_uint(to_tf32(XS[(r0 + g + 8) * XS_STRIDE + kb + t]));
                afr[2] = __float_as_uint(to_tf32(XS[(r0 + g) * XS_STRIDE + kb + t + 4]));
                afr[3] = __float_as_uint(to_tf32(XS[(r0 + g + 8) * XS_STRIDE + kb + t + 4]));
#pragma unroll
                for (int nt = 0; nt < 2; nt++) mma_tf32(acc[mt][nt], afr, bfr[nt]);
            }
        }
        __syncthreads();
    }

    // --- epilogue: stage tile transposed in SMEM, write both outputs coalesced ---
    float* TS = SM;
#pragma unroll
    for (int mt = 0; mt < 2; mt++) {
        const int ja = mrow0 + mt * 16 + g;
        const int jb = ja + 8;
#pragma unroll
        for (int nt = 0; nt < 2; nt++) {
            const int cl = ncol0 + nt * 8 + 2 * t;
            TS[cl * TSW + ja] = acc[mt][nt][0];
            TS[(cl + 1) * TSW + ja] = acc[mt][nt][1];
            TS[cl * TSW + jb] = acc[mt][nt][2];
            TS[(cl + 1) * TSW + jb] = acc[mt][nt][3];
        }
    }
    __syncthreads();

#pragma unroll
    for (int r = 0; r < 8; r++) {
        const int j = wid * 8 + r;
#pragma unroll
        for (int it = 0; it < 2; it++) {
            const int cl = it * 32 + lane;
            g_h[(size_t)(row0 + j) * HOF + col0 + cl] = TS[cl * TSW + j];
        }
    }
    {
        const int hd = col0 >> 7;
        const int f0 = col0 & 127;
#pragma unroll
        for (int r = 0; r < 8; r++) {
            const int cl = wid * 8 + r;
            float* dst = g_hT + ((size_t)hd * OF + f0 + cl) * N + row0;
#pragma unroll
            for (int it = 0; it < 2; it++) {
                const int jd = it * 32 + lane;
                const int jl = (jd & ~7) | kperm_inv(jd);
                dst[jd] = to_tf32(TS[cl * TSW + jl]);
            }
        }
    }
}

// ---------------------------------------------------------------------------
// Kernel B: ci / cj coefficients. One warp per (n,h).
// ---------------------------------------------------------------------------
__global__ __launch_bounds__(128) void k_coeff(const float* __restrict__ a_i,
                                               const float* __restrict__ a_j) {
    const int n = blockIdx.x;
    const int h = threadIdx.x >> 5;
    const int lane = threadIdx.x & 31;

    float4 hv = *(const float4*)&g_h[n * HOF + h * OF + lane * 4];
    float4 ai = *(const float4*)&a_i[h * OF + lane * 4];
    float4 aj = *(const float4*)&a_j[h * OF + lane * 4];
    float si = hv.x * ai.x + hv.y * ai.y + hv.z * ai.z + hv.w * ai.w;
    float sj = hv.x * aj.x + hv.y * aj.y + hv.z * aj.z + hv.w * aj.w;
#pragma unroll
    for (int o = 16; o > 0; o >>= 1) {
        si += __shfl_down_sync(0xffffffffu, si, o);
        sj += __shfl_down_sync(0xffffffffu, sj, o);
    }
    if (lane == 0) {
        g_ci[n * HH + h] = si;
        g_cj[n * HH + h] = sj;
    }
}

// ---------------------------------------------------------------------------
// Kernel D: warp-specialized tf32 attention contraction.
// Warps 0-3 CONSUMERS (MMA, warp tile 32x64); warps 4-7 PRODUCERS
// (adj LDG + exp + P store + H cp.async + z). Named-barrier handshake:
//   producer arrive FULL[s] / consumer sync FULL[s]
//   consumer arrive FREE[s] / producer sync FREE[s]  (pairs i-2 -> i)
// P double-buffered, H 3-stage ring.
// ---------------------------------------------------------------------------
#define D_BM 64
#define D_BK 32
#define NCHUNK (N / D_BK)
#define LDW 40
#define BFULL0 1
#define BFREE0 3

#define OFF_CI   0
#define OFF_BIAS 64
#define OFF_Z    192
#define OFF_H    256                    // 3 stages x 128x40 = 3x5120
#define OFF_P    (OFF_H + 3*5120)       // 2 stages x 64x40  = 2x2560
#define SM_FLOATS (OFF_P + 2*2560)
#define SM_BYTES (SM_FLOATS * 4)

__global__ __launch_bounds__(256, 2) void k_out_tc(const float* __restrict__ adj,
                                                   const float* __restrict__ bias,
                                                   float* __restrict__ out) {
    extern __shared__ float smf[];
    const uint32_t sb = smem_u32(smf);
    const int tid = threadIdx.x;
    const int wid = tid >> 5;
    const int lane = tid & 31;
    const int g = lane >> 2;
    const int t = lane & 3;
    const int i0 = blockIdx.x * D_BM;
    const int head = blockIdx.y;

    if (tid < 64) smf[OFF_CI + tid] = g_ci[(i0 + tid) * HH + head];
    if (tid >= 64 && tid < 192) smf[OFF_BIAS + tid - 64] = bias[head * OF + tid - 64];

    if (wid >= 4) {
        // =================== PRODUCER ===================
        const int pw = wid - 4;              // 0..3
        const int ptid = tid - 128;          // 0..127
        const int hf = ptid >> 3, hq = ptid & 7;   // H cp.async mapping
        const int pcol = ((lane >> 3) << 3) | kperm(lane & 7);
        const float* ci_s = smf + OFF_CI;

        // prologue: H(0) -> stage 0
#pragma unroll
        for (int it = 0; it < 8; it++) {
            int f = hf + 16 * it;
            CP_ASYNC16(sb + (uint32_t)(OFF_H + f * LDW + hq * 4) * 4,
                       g_hT + ((size_t)head * OF + f) * N + hq * 4);
        }
        CP_COMMIT();

        float aval[16], anx[16], zacc[16];
#pragma unroll
        for (int it = 0; it < 16; it++) {
            aval[it] = adj[(size_t)(i0 + pw + 4 * it) * N + lane];
            zacc[it] = 0.0f;
        }
        float cjv = g_cj[(size_t)lane * HH + head];
        float cjn = 0.0f;

        __syncthreads();   // ci/bias staged; everyone aligned

        int pnext = 1;     // H ring stage for H(i+1)
        for (int i = 0; i < NCHUNK; i++) {
            const int s = i & 1;
            // prefetch adj/cj for i+1 (independent of handshakes)
            if (i + 1 < NCHUNK) {
                const int j1 = (i + 1) * D_BK;
#pragma unroll
                for (int it = 0; it < 16; it++)
                    anx[it] = adj[(size_t)(i0 + pw + 4 * it) * N + j1 + lane];
                cjn = g_cj[(size_t)(j1 + lane) * HH + head];
            }

            if (i >= 2) BAR_SYNC(BFREE0 + s);   // consumers done chunk i-2

            // issue H(i+1) into ring stage pnext (old occupant: chunk i-2)
            if (i + 1 < NCHUNK) {
                const int j1 = (i + 1) * D_BK;
                const uint32_t hd = sb + (uint32_t)(OFF_H + pnext * 5120) * 4;
#pragma unroll
                for (int it = 0; it < 8; it++) {
                    int f = hf + 16 * it;
                    CP_ASYNC16(hd + (uint32_t)(f * LDW + hq * 4) * 4,
                               g_hT + ((size_t)head * OF + f) * N + j1 + hq * 4);
                }
            }
            CP_COMMIT();
            CP_WAIT1();     // H(i) complete

            // compute P(i) into stage s
            float* PS = smf + OFF_P + s * 2560;
#pragma unroll
            for (int it = 0; it < 16; it++) {
                const int r = pw + 4 * it;
                float sc = ci_s[r] + cjv;
                sc = fmaxf(sc, SLOPE * sc) * aval[it];
                float e = __expf(sc);
                zacc[it] += e;
                PS[r * LDW + pcol] = to_tf32(e * aval[it]);
            }
            BAR_ARRIVE(BFULL0 + s);

#pragma unroll
            for (int it = 0; it < 16; it++) aval[it] = anx[it];
            cjv = cjn;
            pnext = (pnext == 2) ? 0 : pnext + 1;
        }

        // z reduce: each producer warp owns rows pw+4*it, lanes hold j-partials
#pragma unroll
        for (int it = 0; it < 16; it++) {
            float v = zacc[it];
#pragma unroll
            for (int o = 16; o > 0; o >>= 1) v += __shfl_xor_sync(0xffffffffu, v, o);
            if (lane == 0) smf[OFF_Z + pw + 4 * it] = v;
        }
        __syncthreads();
    } else {
        // =================== CONSUMER ===================
        const int mrow0 = (wid & 1) * 32;
        const int n0w = (wid >> 1) * 64;

        float acc[2][8][4];
#pragma unroll
        for (int a = 0; a < 2; a++)
#pragma unroll
            for (int b = 0; b < 8; b++)
#pragma unroll
                for (int c = 0; c < 4; c++) acc[a][b][c] = 0.0f;

        __syncthreads();   // matches producer's post-prologue barrier

        int hs = 0;
        for (int i = 0; i < NCHUNK; i++) {
            const int s = i & 1;
            BAR_SYNC(BFULL0 + s);          // P(i) + H(i) ready
            const float* PS = smf + OFF_P + s * 2560;
            const float* HS = smf + OFF_H + hs * 5120;
#pragma unroll
            for (int ks = 0; ks < 4; ks++) {
                const int kc = ks * 8 + 2 * t;
                uint32_t bfr[8][2];
#pragma unroll
                for (int nt = 0; nt < 8; nt++) {
                    int n = n0w + nt * 8 + g;
                    float2 bv = *(const float2*)&HS[n * LDW + kc];
                    bfr[nt][0] = __float_as_uint(bv.x);
                    bfr[nt][1] = __float_as_uint(bv.y);
                }
#pragma unroll
                for (int mt = 0; mt < 2; mt++) {
                    int r0 = mrow0 + mt * 16;
                    float2 a0 = *(const float2*)&PS[(r0 + g) * LDW + kc];
                    float2 a1 = *(const float2*)&PS[(r0 + g + 8) * LDW + kc];
                    uint32_t afr[4];
                    afr[0] = __float_as_uint(a0.x);
                    afr[1] = __float_as_uint(a1.x);
                    afr[2] = __float_as_uint(a0.y);
                    afr[3] = __float_as_uint(a1.y);
#pragma unroll
                    for (int nt = 0; nt < 8; nt++) mma_tf32(acc[mt][nt], afr, bfr[nt]);
                }
            }
            BAR_ARRIVE(BFREE0 + s);
            hs = (hs == 2) ? 0 : hs + 1;
        }

        __syncthreads();   // z visible

        const float* biasS = smf + OFF_BIAS;
        const float* zS = smf + OFF_Z;
#pragma unroll
        for (int mt = 0; mt < 2; mt++) {
            const int r = mrow0 + mt * 16 + g;
            const int ra = i0 + r;
            const float za = 1.0f / zS[r];
            const float zb = 1.0f / zS[r + 8];
#pragma unroll
            for (int nt = 0; nt < 8; nt++) {
                const int col = n0w + nt * 8 + 2 * t;
                float2 v0, v1;
                v0.x = acc[mt][nt][0] * za + biasS[col];
                v0.y = acc[mt][nt][1] * za + biasS[col + 1];
                v1.x = acc[mt][nt][2] * zb + biasS[col];
                v1.y = acc[mt][nt][3] * zb + biasS[col + 1];
                *(float2*)&out[(size_t)ra * HOF + head * OF + col] = v0;
                *(float2*)&out[(size_t)(ra + 8) * HOF + head * OF + col] = v1;
            }
        }
    }
}

// ---------------------------------------------------------------------------
extern "C" void kernel_launch(void* const* d_in, const int* in_sizes, int n_in,
                              void* d_out, int out_size) {
    const float* x    = (const float*)d_in[0];   // (4096, 256)
    const float* adj  = (const float*)d_in[1];   // (4096, 4096)
    const float* W    = (const float*)d_in[2];   // (256, 512)
    const float* a_i  = (const float*)d_in[3];   // (4, 128, 1)
    const float* a_j  = (const float*)d_in[4];   // (4, 128, 1)
    const float* bias = (const float*)d_in[5];   // (512,)
    float* out = (float*)d_out;                  // (4096, 512)

    cudaFuncSetAttribute(k_out_tc, cudaFuncAttributeMaxDynamicSharedMemorySize, SM_BYTES);

    dim3 gA(HOF / 64, N / 64);
    k_gemm_h<<<gA, 256>>>(x, W);
    k_coeff<<<N, 128>>>(a_i, a_j);
    dim3 gD(N / D_BM, HH);
    k_out_tc<<<gD, 256, SM_BYTES>>>(adj, bias, out);
}

// round 13
// speedup vs baseline: 1.1568x; 1.1568x over previous
#include <cuda_runtime.h>
#include <cstdint>
#include <math.h>

#define N 4096
#define IN_F 256
#define HH 4
#define OF 128
#define HOF 512
#define SLOPE 0.2f

// Scratch (device globals: no allocations allowed)
__device__ float g_h[N * HOF];           // 8 MB   [n][h*128+f]  (fp32)
__device__ float g_hT[HH * OF * N];      // 8 MB   [h][f][j-permuted] (tf32-rounded)
__device__ float g_ci[N * HH];
__device__ float g_cj[N * HH];

__device__ __forceinline__ uint32_t smem_u32(const void* p) {
    uint32_t a;
    asm("{ .reg .u64 t; cvta.to.shared.u64 t, %1; cvt.u32.u64 %0, t; }" : "=r"(a) : "l"(p));
    return a;
}
__device__ __forceinline__ float to_tf32(float x) {
    float r;
    asm("cvt.rna.tf32.f32 %0, %1;" : "=f"(r) : "f"(x));
    return r;
}
#define CP_ASYNC16(dst_u32, src_ptr) \
    asm volatile("cp.async.cg.shared.global [%0], [%1], 16;" :: "r"(dst_u32), \
                 "l"(__cvta_generic_to_global(src_ptr)))
#define CP_COMMIT() asm volatile("cp.async.commit_group;" ::: "memory")
#define CP_WAIT0()  asm volatile("cp.async.wait_group 0;" ::: "memory")
#define CP_WAIT1()  asm volatile("cp.async.wait_group 1;" ::: "memory")

// m16n8k8 tf32 MMA, D += A*B (row.col)
__device__ __forceinline__ void mma_tf32(float* c, const uint32_t* a, const uint32_t* b) {
    asm volatile(
        "mma.sync.aligned.m16n8k8.row.col.f32.tf32.tf32.f32 "
        "{%0,%1,%2,%3}, {%4,%5,%6,%7}, {%8,%9}, {%0,%1,%2,%3};"
        : "+f"(c[0]), "+f"(c[1]), "+f"(c[2]), "+f"(c[3])
        : "r"(a[0]), "r"(a[1]), "r"(a[2]), "r"(a[3]), "r"(b[0]), "r"(b[1]));
}

// k-pair interleave inside each 8-group: w -> 2*(w&3) + (w>>2); inverse below
__device__ __forceinline__ int kperm(int w) { return ((w & 3) << 1) | ((w >> 2) & 1); }
__device__ __forceinline__ int kperm_inv(int v) { return ((v & 7) >> 1) | ((v & 1) << 2); }

// ---------------------------------------------------------------------------
// Kernel A (tf32 mma, cp.async 2-stage): g_h = x @ W ; g_hT = tf32 transpose.
// (unchanged from R11 — measured 20.4 us)
// ---------------------------------------------------------------------------
#define XS_STRIDE 40
#define WS_STRIDE 72
#define XS_STAGE (64 * XS_STRIDE)      // 2560
#define WS_STAGE (32 * WS_STRIDE)      // 2304
#define TSW 65
__global__ __launch_bounds__(256) void k_gemm_h(const float* __restrict__ X,
                                                const float* __restrict__ W) {
    __shared__ float SM[2 * XS_STAGE + 2 * WS_STAGE];
    const uint32_t sb = smem_u32(SM);
    const int tid = threadIdx.x;
    const int wid = tid >> 5;
    const int lane = tid & 31;
    const int g = lane >> 2;
    const int t = lane & 3;
    const int row0 = blockIdx.y * 64;
    const int col0 = blockIdx.x * 64;
    const int mrow0 = (wid & 1) * 32;
    const int ncol0 = (wid >> 1) * 16;

    const int xm = tid >> 3, xq = tid & 7;
    const int wk = tid >> 4, wn4 = tid & 15;

    {
        const uint32_t xd = sb;
        const uint32_t wd = sb + 2 * XS_STAGE * 4;
#pragma unroll
        for (int it = 0; it < 2; it++) {
            int m = xm + 32 * it;
            CP_ASYNC16(xd + (uint32_t)(m * XS_STRIDE + xq * 4) * 4,
                       X + (size_t)(row0 + m) * IN_F + xq * 4);
            int k = wk + 16 * it;
            CP_ASYNC16(wd + (uint32_t)(k * WS_STRIDE + wn4 * 4) * 4,
                       W + (size_t)k * HOF + col0 + wn4 * 4);
        }
        CP_COMMIT();
    }

    float acc[2][2][4];
#pragma unroll
    for (int a = 0; a < 2; a++)
#pragma unroll
        for (int b = 0; b < 2; b++)
#pragma unroll
            for (int c = 0; c < 4; c++) acc[a][b][c] = 0.0f;

    for (int kk = 0; kk < 8; kk++) {
        const int s = kk & 1;
        if (kk + 1 < 8) {
            const int k0 = (kk + 1) * 32;
            const uint32_t xd = sb + (uint32_t)(((kk + 1) & 1) * XS_STAGE) * 4;
            const uint32_t wd = sb + (uint32_t)(2 * XS_STAGE + ((kk + 1) & 1) * WS_STAGE) * 4;
#pragma unroll
            for (int it = 0; it < 2; it++) {
                int m = xm + 32 * it;
                CP_ASYNC16(xd + (uint32_t)(m * XS_STRIDE + xq * 4) * 4,
                           X + (size_t)(row0 + m) * IN_F + k0 + xq * 4);
                int k = wk + 16 * it;
                CP_ASYNC16(wd + (uint32_t)(k * WS_STRIDE + wn4 * 4) * 4,
                           W + (size_t)(k0 + k) * HOF + col0 + wn4 * 4);
            }
        }
        CP_COMMIT();
        CP_WAIT1();
        __syncthreads();

        const float* XS = SM + s * XS_STAGE;
        const float* WS = SM + 2 * XS_STAGE + s * WS_STAGE;
#pragma unroll
        for (int ks = 0; ks < 4; ks++) {
            const int kb = ks * 8;
            uint32_t bfr[2][2];
#pragma unroll
            for (int nt = 0; nt < 2; nt++) {
                int n = ncol0 + nt * 8 + g;
                bfr[nt][0] = __float_as_uint(to_tf32(WS[(kb + t) * WS_STRIDE + n]));
                bfr[nt][1] = __float_as_uint(to_tf32(WS[(kb + t + 4) * WS_STRIDE + n]));
            }
#pragma unroll
            for (int mt = 0; mt < 2; mt++) {
                int r0 = mrow0 + mt * 16;
                uint32_t afr[4];
                afr[0] = __float_as_uint(to_tf32(XS[(r0 + g) * XS_STRIDE + kb + t]));
                afr[1] = __float_as_uint(to_tf32(XS[(r0 + g + 8) * XS_STRIDE + kb + t]));
                afr[2] = __float_as_uint(to_tf32(XS[(r0 + g) * XS_STRIDE + kb + t + 4]));
                afr[3] = __float_as_uint(to_tf32(XS[(r0 + g + 8) * XS_STRIDE + kb + t + 4]));
#pragma unroll
                for (int nt = 0; nt < 2; nt++) mma_tf32(acc[mt][nt], afr, bfr[nt]);
            }
        }
        __syncthreads();
    }

    float* TS = SM;
#pragma unroll
    for (int mt = 0; mt < 2; mt++) {
        const int ja = mrow0 + mt * 16 + g;
        const int jb = ja + 8;
#pragma unroll
        for (int nt = 0; nt < 2; nt++) {
            const int cl = ncol0 + nt * 8 + 2 * t;
            TS[cl * TSW + ja] = acc[mt][nt][0];
            TS[(cl + 1) * TSW + ja] = acc[mt][nt][1];
            TS[cl * TSW + jb] = acc[mt][nt][2];
            TS[(cl + 1) * TSW + jb] = acc[mt][nt][3];
        }
    }
    __syncthreads();

#pragma unroll
    for (int r = 0; r < 8; r++) {
        const int j = wid * 8 + r;
#pragma unroll
        for (int it = 0; it < 2; it++) {
            const int cl = it * 32 + lane;
            g_h[(size_t)(row0 + j) * HOF + col0 + cl] = TS[cl * TSW + j];
        }
    }
    {
        const int hd = col0 >> 7;
        const int f0 = col0 & 127;
#pragma unroll
        for (int r = 0; r < 8; r++) {
            const int cl = wid * 8 + r;
            float* dst = g_hT + ((size_t)hd * OF + f0 + cl) * N + row0;
#pragma unroll
            for (int it = 0; it < 2; it++) {
                const int jd = it * 32 + lane;
                const int jl = (jd & ~7) | kperm_inv(jd);
                dst[jd] = to_tf32(TS[cl * TSW + jl]);
            }
        }
    }
}

// ---------------------------------------------------------------------------
// Kernel B: ci / cj coefficients. One warp per (n,h).
// ---------------------------------------------------------------------------
__global__ __launch_bounds__(128) void k_coeff(const float* __restrict__ a_i,
                                               const float* __restrict__ a_j) {
    const int n = blockIdx.x;
    const int h = threadIdx.x >> 5;
    const int lane = threadIdx.x & 31;

    float4 hv = *(const float4*)&g_h[n * HOF + h * OF + lane * 4];
    float4 ai = *(const float4*)&a_i[h * OF + lane * 4];
    float4 aj = *(const float4*)&a_j[h * OF + lane * 4];
    float si = hv.x * ai.x + hv.y * ai.y + hv.z * ai.z + hv.w * ai.w;
    float sj = hv.x * aj.x + hv.y * aj.y + hv.z * aj.z + hv.w * aj.w;
#pragma unroll
    for (int o = 16; o > 0; o >>= 1) {
        si += __shfl_down_sync(0xffffffffu, si, o);
        sj += __shfl_down_sync(0xffffffffu, sj, o);
    }
    if (lane == 0) {
        g_ci[n * HH + h] = si;
        g_cj[n * HH + h] = sj;
    }
}

// ---------------------------------------------------------------------------
// Kernel D (R9 homogeneous structure, 2-stage H, 3 CTAs/SM):
// per chunk: prefetch adj(i+1) regs -> P(i) -> wait H(i) -> bar ->
//            issue H(i+1) -> mma(i).  One __syncthreads per chunk.
// H 2-stage (issue moved after bar makes this race-free); P 2-stage.
// SMEM 62.5KB/CTA -> 3 CTAs resident.
// ---------------------------------------------------------------------------
#define D_BM 64
#define D_BK 32
#define NCHUNK (N / D_BK)
#define LDW 40

#define OFF_CI   0
#define OFF_BIAS 64
#define OFF_Z    192
#define OFF_H    256                    // 2 stages x 128x40 = 2x5120
#define OFF_P    (OFF_H + 2*5120)       // 2 stages x 64x40  = 2x2560
#define SM_FLOATS (OFF_P + 2*2560)
#define SM_BYTES (SM_FLOATS * 4)

__global__ __launch_bounds__(256, 3) void k_out_tc(const float* __restrict__ adj,
                                                   const float* __restrict__ bias,
                                                   float* __restrict__ out) {
    extern __shared__ float smf[];
    const uint32_t sb = smem_u32(smf);
    const int tid = threadIdx.x;
    const int wid = tid >> 5;
    const int lane = tid & 31;
    const int g = lane >> 2;
    const int t = lane & 3;
    const int i0 = blockIdx.x * D_BM;
    const int head = blockIdx.y;
    const int mrow0 = (wid & 1) * 32;
    const int n0w = (wid >> 1) * 32;

    if (tid < 64) smf[OFF_CI + tid] = g_ci[(i0 + tid) * HH + head];
    if (tid >= 64 && tid < 192) smf[OFF_BIAS + tid - 64] = bias[head * OF + tid - 64];

    // prologue: H(0) -> stage 0
    {
        const uint32_t h_dst = sb + (OFF_H) * 4;
#pragma unroll
        for (int it = 0; it < 4; it++) {
            int idx = tid + 256 * it;
            int f = idx >> 3, q = idx & 7;
            CP_ASYNC16(h_dst + (uint32_t)(f * LDW + q * 4) * 4,
                       g_hT + ((size_t)head * OF + f) * N + q * 4);
        }
        CP_COMMIT();
    }

    // adj + cj for chunk 0
    float aval[8];
#pragma unroll
    for (int it = 0; it < 8; it++)
        aval[it] = adj[(size_t)(i0 + wid + 8 * it) * N + lane];
    float cjv = g_cj[(size_t)lane * HH + head];

    __syncthreads();

    float acc[2][4][4];
#pragma unroll
    for (int a = 0; a < 2; a++)
#pragma unroll
        for (int b = 0; b < 4; b++)
#pragma unroll
            for (int c = 0; c < 4; c++) acc[a][b][c] = 0.0f;
    float zacc[8];
#pragma unroll
    for (int it = 0; it < 8; it++) zacc[it] = 0.0f;

    const float* ci_s = smf + OFF_CI;
    const int pcol = ((lane >> 3) << 3) | kperm(lane & 7);

    for (int i = 0; i < NCHUNK; i++) {
        const int s = i & 1;
        const int j0 = i * D_BK;

        // prefetch adj/cj for chunk i+1 (registers)
        float anx[8];
        float cjn = 0.0f;
        if (i + 1 < NCHUNK) {
#pragma unroll
            for (int it = 0; it < 8; it++)
                anx[it] = adj[(size_t)(i0 + wid + 8 * it) * N + j0 + D_BK + lane];
            cjn = g_cj[(size_t)(j0 + D_BK + lane) * HH + head];
        }

        // P(i) into stage s (stage free: mma(i-2) finished before bar(i-1))
        float* PS = smf + OFF_P + s * 2560;
#pragma unroll
        for (int it = 0; it < 8; it++) {
            const int r = wid + 8 * it;
            float sc = ci_s[r] + cjv;
            sc = fmaxf(sc, SLOPE * sc) * aval[it];
            float e = __expf(sc);
            zacc[it] += e;
            PS[r * LDW + pcol] = to_tf32(e * aval[it]);
        }
#pragma unroll
        for (int it = 0; it < 8; it++) aval[it] = anx[it];
        cjv = cjn;

        CP_WAIT0();       // pending = {H(i)} exactly -> H(i) complete
        __syncthreads();  // P(i)+H(i) visible to all; mma(i-1) done everywhere

        // issue H(i+1) into stage s^1 (safe: its readers were mma(i-1))
        if (i + 1 < NCHUNK) {
            const uint32_t h_dst = sb + (uint32_t)(OFF_H + (s ^ 1) * 5120) * 4;
            const int j1 = j0 + D_BK;
#pragma unroll
            for (int it = 0; it < 4; it++) {
                int idx = tid + 256 * it;
                int f = idx >> 3, q = idx & 7;
                CP_ASYNC16(h_dst + (uint32_t)(f * LDW + q * 4) * 4,
                           g_hT + ((size_t)head * OF + f) * N + j1 + q * 4);
            }
            CP_COMMIT();
        }

        // mma(i): PS(s) x HS(s)
        const float* HS = smf + OFF_H + s * 5120;
#pragma unroll
        for (int ks = 0; ks < 4; ks++) {
            const int kc = ks * 8 + 2 * t;
            uint32_t bfr[4][2];
#pragma unroll
            for (int nt = 0; nt < 4; nt++) {
                int n = n0w + nt * 8 + g;
                float2 bv = *(const float2*)&HS[n * LDW + kc];
                bfr[nt][0] = __float_as_uint(bv.x);
                bfr[nt][1] = __float_as_uint(bv.y);
            }
#pragma unroll
            for (int mt = 0; mt < 2; mt++) {
                int r0 = mrow0 + mt * 16;
                float2 a0 = *(const float2*)&PS[(r0 + g) * LDW + kc];
                float2 a1 = *(const float2*)&PS[(r0 + g + 8) * LDW + kc];
                uint32_t afr[4];
                afr[0] = __float_as_uint(a0.x);
                afr[1] = __float_as_uint(a1.x);
                afr[2] = __float_as_uint(a0.y);
                afr[3] = __float_as_uint(a1.y);
#pragma unroll
                for (int nt = 0; nt < 4; nt++) mma_tf32(acc[mt][nt], afr, bfr[nt]);
            }
        }
    }

    // z: reduce across lanes (each warp owns rows wid+8*it)
#pragma unroll
    for (int it = 0; it < 8; it++) {
        float v = zacc[it];
#pragma unroll
        for (int o = 16; o > 0; o >>= 1) v += __shfl_xor_sync(0xffffffffu, v, o);
        if (lane == 0) smf[OFF_Z + wid + 8 * it] = v;
    }
    __syncthreads();

    // epilogue: scale by 1/z, add bias
    const float* biasS = smf + OFF_BIAS;
    const float* zS = smf + OFF_Z;
#pragma unroll
    for (int mt = 0; mt < 2; mt++) {
        const int r = mrow0 + mt * 16 + g;
        const int ra = i0 + r;
        const float za = 1.0f / zS[r];
        const float zb = 1.0f / zS[r + 8];
#pragma unroll
        for (int nt = 0; nt < 4; nt++) {
            const int col = n0w + nt * 8 + 2 * t;
            float2 v0, v1;
            v0.x = acc[mt][nt][0] * za + biasS[col];
            v0.y = acc[mt][nt][1] * za + biasS[col + 1];
            v1.x = acc[mt][nt][2] * zb + biasS[col];
            v1.y = acc[mt][nt][3] * zb + biasS[col + 1];
            *(float2*)&out[(size_t)ra * HOF + head * OF + col] = v0;
            *(float2*)&out[(size_t)(ra + 8) * HOF + head * OF + col] = v1;
        }
    }
}

// ---------------------------------------------------------------------------
extern "C" void kernel_launch(void* const* d_in, const int* in_sizes, int n_in,
                              void* d_out, int out_size) {
    const float* x    = (const float*)d_in[0];   // (4096, 256)
    const float* adj  = (const float*)d_in[1];   // (4096, 4096)
    const float* W    = (const float*)d_in[2];   // (256, 512)
    const float* a_i  = (const float*)d_in[3];   // (4, 128, 1)
    const float* a_j  = (const float*)d_in[4];   // (4, 128, 1)
    const float* bias = (const float*)d_in[5];   // (512,)
    float* out = (float*)d_out;                  // (4096, 512)

    cudaFuncSetAttribute(k_out_tc, cudaFuncAttributeMaxDynamicSharedMemorySize, SM_BYTES);

    dim3 gA(HOF / 64, N / 64);
    k_gemm_h<<<gA, 256>>>(x, W);
    k_coeff<<<N, 128>>>(a_i, a_j);
    dim3 gD(N / D_BM, HH);
    k_out_tc<<<gD, 256, SM_BYTES>>>(adj, bias, out);
}

// round 14
// speedup vs baseline: 1.5384x; 1.3299x over previous
#include <cuda_runtime.h>
#include <cstdint>
#include <math.h>

#define N 4096
#define IN_F 256
#define HH 4
#define OF 128
#define HOF 512
#define SLOPE 0.2f

// Scratch (device globals: no allocations allowed)
__device__ float g_h[N * HOF];                 // 8 MB  [n][h*128+f] (fp32)
__device__ uint32_t g_hTb[HH * OF * (N / 2)];  // 4 MB  [h][f][j-pair, kperm'd] bf16x2
__device__ float g_cih[HH * N];                // head-major ci
__device__ float g_cjh[HH * N];                // head-major cj

__device__ __forceinline__ uint32_t smem_u32(const void* p) {
    uint32_t a;
    asm("{ .reg .u64 t; cvta.to.shared.u64 t, %1; cvt.u32.u64 %0, t; }" : "=r"(a) : "l"(p));
    return a;
}
__device__ __forceinline__ float to_tf32(float x) {
    float r;
    asm("cvt.rna.tf32.f32 %0, %1;" : "=f"(r) : "f"(x));
    return r;
}
__device__ __forceinline__ uint32_t pack_bf16x2(float hi, float lo) {
    uint32_t d;
    asm("cvt.rn.bf16x2.f32 %0, %1, %2;" : "=r"(d) : "f"(hi), "f"(lo));
    return d;
}
#define CP_ASYNC16(dst_u32, src_ptr) \
    asm volatile("cp.async.cg.shared.global [%0], [%1], 16;" :: "r"(dst_u32), \
                 "l"(__cvta_generic_to_global(src_ptr)))
#define CP_COMMIT() asm volatile("cp.async.commit_group;" ::: "memory")
#define CP_WAIT0()  asm volatile("cp.async.wait_group 0;" ::: "memory")
#define CP_WAIT1()  asm volatile("cp.async.wait_group 1;" ::: "memory")

// tf32 m16n8k8 (kernel A only)
__device__ __forceinline__ void mma_tf32(float* c, const uint32_t* a, const uint32_t* b) {
    asm volatile(
        "mma.sync.aligned.m16n8k8.row.col.f32.tf32.tf32.f32 "
        "{%0,%1,%2,%3}, {%4,%5,%6,%7}, {%8,%9}, {%0,%1,%2,%3};"
        : "+f"(c[0]), "+f"(c[1]), "+f"(c[2]), "+f"(c[3])
        : "r"(a[0]), "r"(a[1]), "r"(a[2]), "r"(a[3]), "r"(b[0]), "r"(b[1]));
}
// bf16 m16n8k16 (kernel D)
__device__ __forceinline__ void mma_bf16(float* c, const uint32_t* a, const uint32_t* b) {
    asm volatile(
        "mma.sync.aligned.m16n8k16.row.col.f32.bf16.bf16.f32 "
        "{%0,%1,%2,%3}, {%4,%5,%6,%7}, {%8,%9}, {%0,%1,%2,%3};"
        : "+f"(c[0]), "+f"(c[1]), "+f"(c[2]), "+f"(c[3])
        : "r"(a[0]), "r"(a[1]), "r"(a[2]), "r"(a[3]), "r"(b[0]), "r"(b[1]));
}

// interleave inside each 8-group: u -> 2*(u&3) + (u>>2)
__device__ __forceinline__ int kperm(int w) { return ((w & 3) << 1) | ((w >> 2) & 1); }

// ---------------------------------------------------------------------------
// Kernel A (tf32 mma, cp.async 2-stage): g_h = x @ W ; g_hTb = bf16x2 transpose
// ---------------------------------------------------------------------------
#define XS_STRIDE 40
#define WS_STRIDE 72
#define XS_STAGE (64 * XS_STRIDE)
#define WS_STAGE (32 * WS_STRIDE)
#define TSW 65
__global__ __launch_bounds__(256) void k_gemm_h(const float* __restrict__ X,
                                                const float* __restrict__ W) {
    __shared__ float SM[2 * XS_STAGE + 2 * WS_STAGE];
    const uint32_t sb = smem_u32(SM);
    const int tid = threadIdx.x;
    const int wid = tid >> 5;
    const int lane = tid & 31;
    const int g = lane >> 2;
    const int t = lane & 3;
    const int row0 = blockIdx.y * 64;
    const int col0 = blockIdx.x * 64;
    const int mrow0 = (wid & 1) * 32;
    const int ncol0 = (wid >> 1) * 16;

    const int xm = tid >> 3, xq = tid & 7;
    const int wk = tid >> 4, wn4 = tid & 15;

    {
        const uint32_t xd = sb;
        const uint32_t wd = sb + 2 * XS_STAGE * 4;
#pragma unroll
        for (int it = 0; it < 2; it++) {
            int m = xm + 32 * it;
            CP_ASYNC16(xd + (uint32_t)(m * XS_STRIDE + xq * 4) * 4,
                       X + (size_t)(row0 + m) * IN_F + xq * 4);
            int k = wk + 16 * it;
            CP_ASYNC16(wd + (uint32_t)(k * WS_STRIDE + wn4 * 4) * 4,
                       W + (size_t)k * HOF + col0 + wn4 * 4);
        }
        CP_COMMIT();
    }

    float acc[2][2][4];
#pragma unroll
    for (int a = 0; a < 2; a++)
#pragma unroll
        for (int b = 0; b < 2; b++)
#pragma unroll
            for (int c = 0; c < 4; c++) acc[a][b][c] = 0.0f;

    for (int kk = 0; kk < 8; kk++) {
        const int s = kk & 1;
        if (kk + 1 < 8) {
            const int k0 = (kk + 1) * 32;
            const uint32_t xd = sb + (uint32_t)(((kk + 1) & 1) * XS_STAGE) * 4;
            const uint32_t wd = sb + (uint32_t)(2 * XS_STAGE + ((kk + 1) & 1) * WS_STAGE) * 4;
#pragma unroll
            for (int it = 0; it < 2; it++) {
                int m = xm + 32 * it;
                CP_ASYNC16(xd + (uint32_t)(m * XS_STRIDE + xq * 4) * 4,
                           X + (size_t)(row0 + m) * IN_F + k0 + xq * 4);
                int k = wk + 16 * it;
                CP_ASYNC16(wd + (uint32_t)(k * WS_STRIDE + wn4 * 4) * 4,
                           W + (size_t)(k0 + k) * HOF + col0 + wn4 * 4);
            }
        }
        CP_COMMIT();
        CP_WAIT1();
        __syncthreads();

        const float* XS = SM + s * XS_STAGE;
        const float* WS = SM + 2 * XS_STAGE + s * WS_STAGE;
#pragma unroll
        for (int ks = 0; ks < 4; ks++) {
            const int kb = ks * 8;
            uint32_t bfr[2][2];
#pragma unroll
            for (int nt = 0; nt < 2; nt++) {
                int n = ncol0 + nt * 8 + g;
                bfr[nt][0] = __float_as_uint(to_tf32(WS[(kb + t) * WS_STRIDE + n]));
                bfr[nt][1] = __float_as_uint(to_tf32(WS[(kb + t + 4) * WS_STRIDE + n]));
            }
#pragma unroll
            for (int mt = 0; mt < 2; mt++) {
                int r0 = mrow0 + mt * 16;
                uint32_t afr[4];
                afr[0] = __float_as_uint(to_tf32(XS[(r0 + g) * XS_STRIDE + kb + t]));
                afr[1] = __float_as_uint(to_tf32(XS[(r0 + g + 8) * XS_STRIDE + kb + t]));
                afr[2] = __float_as_uint(to_tf32(XS[(r0 + g) * XS_STRIDE + kb + t + 4]));
                afr[3] = __float_as_uint(to_tf32(XS[(r0 + g + 8) * XS_STRIDE + kb + t + 4]));
#pragma unroll
                for (int nt = 0; nt < 2; nt++) mma_tf32(acc[mt][nt], afr, bfr[nt]);
            }
        }
        __syncthreads();
    }

    float* TS = SM;
#pragma unroll
    for (int mt = 0; mt < 2; mt++) {
        const int ja = mrow0 + mt * 16 + g;
        const int jb = ja + 8;
#pragma unroll
        for (int nt = 0; nt < 2; nt++) {
            const int cl = ncol0 + nt * 8 + 2 * t;
            TS[cl * TSW + ja] = acc[mt][nt][0];
            TS[(cl + 1) * TSW + ja] = acc[mt][nt][1];
            TS[cl * TSW + jb] = acc[mt][nt][2];
            TS[(cl + 1) * TSW + jb] = acc[mt][nt][3];
        }
    }
    __syncthreads();

    // g_h rows (coalesced)
#pragma unroll
    for (int r = 0; r < 8; r++) {
        const int j = wid * 8 + r;
#pragma unroll
        for (int it = 0; it < 2; it++) {
            const int cl = it * 32 + lane;
            g_h[(size_t)(row0 + j) * HOF + col0 + cl] = TS[cl * TSW + j];
        }
    }
    // g_hTb: bf16x2 pairs, kperm'd within each 8-pair (16-j) group
    {
        const int hd = col0 >> 7;
        const int f0 = col0 & 127;
        const int p = lane;                           // pair 0..31
        const int pos = (p & ~7) | kperm(p & 7);
#pragma unroll
        for (int r = 0; r < 8; r++) {
            const int cl = wid * 8 + r;
            uint32_t* dst = g_hTb + ((size_t)hd * OF + f0 + cl) * (N / 2) + row0 / 2;
            float lo = TS[cl * TSW + 2 * p];
            float hi = TS[cl * TSW + 2 * p + 1];
            dst[pos] = pack_bf16x2(hi, lo);
        }
    }
}

// ---------------------------------------------------------------------------
// Kernel B: ci / cj coefficients (head-major outputs). One warp per (n,h).
// ---------------------------------------------------------------------------
__global__ __launch_bounds__(128) void k_coeff(const float* __restrict__ a_i,
                                               const float* __restrict__ a_j) {
    const int n = blockIdx.x;
    const int h = threadIdx.x >> 5;
    const int lane = threadIdx.x & 31;

    float4 hv = *(const float4*)&g_h[n * HOF + h * OF + lane * 4];
    float4 ai = *(const float4*)&a_i[h * OF + lane * 4];
    float4 aj = *(const float4*)&a_j[h * OF + lane * 4];
    float si = hv.x * ai.x + hv.y * ai.y + hv.z * ai.z + hv.w * ai.w;
    float sj = hv.x * aj.x + hv.y * aj.y + hv.z * aj.z + hv.w * aj.w;
#pragma unroll
    for (int o = 16; o > 0; o >>= 1) {
        si += __shfl_down_sync(0xffffffffu, si, o);
        sj += __shfl_down_sync(0xffffffffu, sj, o);
    }
    if (lane == 0) {
        g_cih[h * N + n] = si;
        g_cjh[h * N + n] = sj;
    }
}

// ---------------------------------------------------------------------------
// Kernel D (bf16 m16n8k16, R12 skeleton): per chunk:
//   prefetch adj/cj(i+1) regs -> P(i) bf16x2 -> wait H(i) -> bar ->
//   issue H(i+1) -> mma(i).   3 CTAs/SM; strides 24 words (conflict-free .64).
// ---------------------------------------------------------------------------
#define D_BM 64
#define D_BK 32
#define NCHUNK (N / D_BK)
#define LDW 24                           // uint32 stride (16 used + 8 pad)

#define OFF_CI   0
#define OFF_BIAS 64
#define OFF_Z    192
#define OFF_H    256                     // 2 stages x 128x24 u32 = 2x3072
#define OFF_P    (OFF_H + 2*3072)        // 2 stages x 64x24 u32  = 2x1536
#define SM_WORDS (OFF_P + 2*1536)
#define SM_BYTES (SM_WORDS * 4)

__global__ __launch_bounds__(256, 3) void k_out_tc(const float* __restrict__ adj,
                                                   const float* __restrict__ bias,
                                                   float* __restrict__ out) {
    extern __shared__ float smf[];
    uint32_t* smu = (uint32_t*)smf;
    const uint32_t sb = smem_u32(smf);
    const int tid = threadIdx.x;
    const int wid = tid >> 5;
    const int lane = tid & 31;
    const int g = lane >> 2;
    const int t = lane & 3;
    const int i0 = blockIdx.x * D_BM;
    const int head = blockIdx.y;
    const int mrow0 = (wid & 1) * 32;
    const int n0w = (wid >> 1) * 32;

    if (tid < 64) smf[OFF_CI + tid] = g_cih[head * N + i0 + tid];
    if (tid >= 64 && tid < 192) smf[OFF_BIAS + tid - 64] = bias[head * OF + tid - 64];

    // prologue: H(0) -> stage 0  (8KB payload: 512 cp.async16, 2/thread)
    {
        const uint32_t h_dst = sb + (OFF_H) * 4;
#pragma unroll
        for (int it = 0; it < 2; it++) {
            int idx = tid + 256 * it;
            int f = idx >> 2, q = idx & 3;
            CP_ASYNC16(h_dst + (uint32_t)(f * LDW + q * 4) * 4,
                       g_hTb + ((size_t)head * OF + f) * (N / 2) + q * 4);
        }
        CP_COMMIT();
    }

    // P-producer indices: 16 threads/row; thread -> (r = tid>>4 (+16it), jp = tid&15)
    const int prow = tid >> 4;            // 0..15
    const int jp = tid & 15;              // pair within chunk
    const int pcol = ((jp >> 3) << 3) | kperm(jp & 7);

    // adj + cj for chunk 0 (float2 per (r,it))
    float2 aval[4];
#pragma unroll
    for (int it = 0; it < 4; it++)
        aval[it] = *(const float2*)&adj[(size_t)(i0 + prow + 16 * it) * N + 2 * jp];
    float2 cjv = *(const float2*)&g_cjh[head * N + 2 * jp];

    __syncthreads();

    float acc[2][4][4];
#pragma unroll
    for (int a = 0; a < 2; a++)
#pragma unroll
        for (int b = 0; b < 4; b++)
#pragma unroll
            for (int c = 0; c < 4; c++) acc[a][b][c] = 0.0f;
    float zacc[4];
#pragma unroll
    for (int it = 0; it < 4; it++) zacc[it] = 0.0f;

    const float* ci_s = smf + OFF_CI;

    for (int i = 0; i < NCHUNK; i++) {
        const int s = i & 1;
        const int j0 = i * D_BK;

        // prefetch adj/cj for chunk i+1
        float2 anx[4];
        float2 cjn = make_float2(0.f, 0.f);
        if (i + 1 < NCHUNK) {
#pragma unroll
            for (int it = 0; it < 4; it++)
                anx[it] = *(const float2*)&adj[(size_t)(i0 + prow + 16 * it) * N +
                                               j0 + D_BK + 2 * jp];
            cjn = *(const float2*)&g_cjh[head * N + j0 + D_BK + 2 * jp];
        }

        // P(i) into stage s
        uint32_t* PS = smu + OFF_P + s * 1536;
#pragma unroll
        for (int it = 0; it < 4; it++) {
            const int r = prow + 16 * it;
            const float civ = ci_s[r];
            float s0 = civ + cjv.x;
            float s1 = civ + cjv.y;
            s0 = fmaxf(s0, SLOPE * s0) * aval[it].x;
            s1 = fmaxf(s1, SLOPE * s1) * aval[it].y;
            float e0 = __expf(s0);
            float e1 = __expf(s1);
            zacc[it] += e0 + e1;
            PS[r * LDW + pcol] = pack_bf16x2(e1 * aval[it].y, e0 * aval[it].x);
        }
#pragma unroll
        for (int it = 0; it < 4; it++) aval[it] = anx[it];
        cjv = cjn;

        CP_WAIT0();       // pending = {H(i)} exactly
        __syncthreads();  // P(i)+H(i) visible; mma(i-1) done everywhere

        // issue H(i+1) into stage s^1 (its readers were mma(i-1))
        if (i + 1 < NCHUNK) {
            const uint32_t h_dst = sb + (uint32_t)(OFF_H + (s ^ 1) * 3072) * 4;
            const int jp1 = (j0 + D_BK) / 2;
#pragma unroll
            for (int it = 0; it < 2; it++) {
                int idx = tid + 256 * it;
                int f = idx >> 2, q = idx & 3;
                CP_ASYNC16(h_dst + (uint32_t)(f * LDW + q * 4) * 4,
                           g_hTb + ((size_t)head * OF + f) * (N / 2) + jp1 + q * 4);
            }
            CP_COMMIT();
        }

        // mma(i): 2 k-steps of 16
        const uint32_t* HS = smu + OFF_H + s * 3072;
#pragma unroll
        for (int ks = 0; ks < 2; ks++) {
            const int kc = ks * 8 + 2 * t;
            uint32_t bfr[4][2];
#pragma unroll
            for (int nt = 0; nt < 4; nt++) {
                int n = n0w + nt * 8 + g;
                *(uint2*)bfr[nt] = *(const uint2*)&HS[n * LDW + kc];
            }
            uint32_t* PSb = (uint32_t*)(smu + OFF_P + s * 1536);
#pragma unroll
            for (int mt = 0; mt < 2; mt++) {
                int r0 = mrow0 + mt * 16;
                uint2 a0 = *(const uint2*)&PSb[(r0 + g) * LDW + kc];
                uint2 a1 = *(const uint2*)&PSb[(r0 + g + 8) * LDW + kc];
                uint32_t afr[4] = {a0.x, a1.x, a0.y, a1.y};
#pragma unroll
                for (int nt = 0; nt < 4; nt++) mma_bf16(acc[mt][nt], afr, bfr[nt]);
            }
        }
    }

    // z reduce: 16 lanes share a row (xor 1..8 within each half-warp)
#pragma unroll
    for (int it = 0; it < 4; it++) {
        float v = zacc[it];
#pragma unroll
        for (int o = 8; o > 0; o >>= 1) v += __shfl_xor_sync(0xffffffffu, v, o);
        if ((lane & 15) == 0) smf[OFF_Z + prow + 16 * it] = v;
    }
    __syncthreads();

    // epilogue: scale by 1/z, add bias
    const float* biasS = smf + OFF_BIAS;
    const float* zS = smf + OFF_Z;
#pragma unroll
    for (int mt = 0; mt < 2; mt++) {
        const int r = mrow0 + mt * 16 + g;
        const int ra = i0 + r;
        const float za = 1.0f / zS[r];
        const float zb = 1.0f / zS[r + 8];
#pragma unroll
        for (int nt = 0; nt < 4; nt++) {
            const int col = n0w + nt * 8 + 2 * t;
            float2 v0, v1;
            v0.x = acc[mt][nt][0] * za + biasS[col];
            v0.y = acc[mt][nt][1] * za + biasS[col + 1];
            v1.x = acc[mt][nt][2] * zb + biasS[col];
            v1.y = acc[mt][nt][3] * zb + biasS[col + 1];
            *(float2*)&out[(size_t)ra * HOF + head * OF + col] = v0;
            *(float2*)&out[(size_t)(ra + 8) * HOF + head * OF + col] = v1;
        }
    }
}

// ---------------------------------------------------------------------------
extern "C" void kernel_launch(void* const* d_in, const int* in_sizes, int n_in,
                              void* d_out, int out_size) {
    const float* x    = (const float*)d_in[0];   // (4096, 256)
    const float* adj  = (const float*)d_in[1];   // (4096, 4096)
    const float* W    = (const float*)d_in[2];   // (256, 512)
    const float* a_i  = (const float*)d_in[3];   // (4, 128, 1)
    const float* a_j  = (const float*)d_in[4];   // (4, 128, 1)
    const float* bias = (const float*)d_in[5];   // (512,)
    float* out = (float*)d_out;                  // (4096, 512)

    cudaFuncSetAttribute(k_out_tc, cudaFuncAttributeMaxDynamicSharedMemorySize, SM_BYTES);

    dim3 gA(HOF / 64, N / 64);
    k_gemm_h<<<gA, 256>>>(x, W);
    k_coeff<<<N, 128>>>(a_i, a_j);
    dim3 gD(N / D_BM, HH);
    k_out_tc<<<gD, 256, SM_BYTES>>>(adj, bias, out);
}

// round 15
// speedup vs baseline: 1.6342x; 1.0623x over previous
#include <cuda_runtime.h>
#include <cstdint>
#include <math.h>

#define N 4096
#define IN_F 256
#define HH 4
#define OF 128
#define HOF 512
#define SLOPE 0.2f

// Scratch (device globals: no allocations allowed)
__device__ float g_h[N * HOF];                 // 8 MB  [n][h*128+f] (fp32)
__device__ uint32_t g_hTb[HH * OF * (N / 2)];  // 4 MB  [h][f][j-pair, kperm'd] bf16x2
__device__ float g_cih[HH * N];                // head-major ci
__device__ float g_cjh[HH * N];                // head-major cj

__device__ __forceinline__ uint32_t smem_u32(const void* p) {
    uint32_t a;
    asm("{ .reg .u64 t; cvta.to.shared.u64 t, %1; cvt.u32.u64 %0, t; }" : "=r"(a) : "l"(p));
    return a;
}
__device__ __forceinline__ float to_tf32(float x) {
    float r;
    asm("cvt.rna.tf32.f32 %0, %1;" : "=f"(r) : "f"(x));
    return r;
}
__device__ __forceinline__ uint32_t pack_bf16x2(float hi, float lo) {
    uint32_t d;
    asm("cvt.rn.bf16x2.f32 %0, %1, %2;" : "=r"(d) : "f"(hi), "f"(lo));
    return d;
}
#define CP_ASYNC16(dst_u32, src_ptr) \
    asm volatile("cp.async.cg.shared.global [%0], [%1], 16;" :: "r"(dst_u32), \
                 "l"(__cvta_generic_to_global(src_ptr)))
#define CP_COMMIT() asm volatile("cp.async.commit_group;" ::: "memory")
#define CP_WAIT0()  asm volatile("cp.async.wait_group 0;" ::: "memory")
#define CP_WAIT1()  asm volatile("cp.async.wait_group 1;" ::: "memory")

// tf32 m16n8k8 (kernel A only)
__device__ __forceinline__ void mma_tf32(float* c, const uint32_t* a, const uint32_t* b) {
    asm volatile(
        "mma.sync.aligned.m16n8k8.row.col.f32.tf32.tf32.f32 "
        "{%0,%1,%2,%3}, {%4,%5,%6,%7}, {%8,%9}, {%0,%1,%2,%3};"
        : "+f"(c[0]), "+f"(c[1]), "+f"(c[2]), "+f"(c[3])
        : "r"(a[0]), "r"(a[1]), "r"(a[2]), "r"(a[3]), "r"(b[0]), "r"(b[1]));
}
// bf16 m16n8k16 (kernel D)
__device__ __forceinline__ void mma_bf16(float* c, const uint32_t* a, const uint32_t* b) {
    asm volatile(
        "mma.sync.aligned.m16n8k16.row.col.f32.bf16.bf16.f32 "
        "{%0,%1,%2,%3}, {%4,%5,%6,%7}, {%8,%9}, {%0,%1,%2,%3};"
        : "+f"(c[0]), "+f"(c[1]), "+f"(c[2]), "+f"(c[3])
        : "r"(a[0]), "r"(a[1]), "r"(a[2]), "r"(a[3]), "r"(b[0]), "r"(b[1]));
}

// interleave inside each 8-group: u -> 2*(u&3) + (u>>2)
__device__ __forceinline__ int kperm(int w) { return ((w & 3) << 1) | ((w >> 2) & 1); }

// ---------------------------------------------------------------------------
// Kernel A (tf32 mma, cp.async 2-stage): g_h = x @ W ; g_hTb = bf16x2 transpose
// (unchanged — measured 20.2 us)
// ---------------------------------------------------------------------------
#define XS_STRIDE 40
#define WS_STRIDE 72
#define XS_STAGE (64 * XS_STRIDE)
#define WS_STAGE (32 * WS_STRIDE)
#define TSW 65
__global__ __launch_bounds__(256) void k_gemm_h(const float* __restrict__ X,
                                                const float* __restrict__ W) {
    __shared__ float SM[2 * XS_STAGE + 2 * WS_STAGE];
    const uint32_t sb = smem_u32(SM);
    const int tid = threadIdx.x;
    const int wid = tid >> 5;
    const int lane = tid & 31;
    const int g = lane >> 2;
    const int t = lane & 3;
    const int row0 = blockIdx.y * 64;
    const int col0 = blockIdx.x * 64;
    const int mrow0 = (wid & 1) * 32;
    const int ncol0 = (wid >> 1) * 16;

    const int xm = tid >> 3, xq = tid & 7;
    const int wk = tid >> 4, wn4 = tid & 15;

    {
        const uint32_t xd = sb;
        const uint32_t wd = sb + 2 * XS_STAGE * 4;
#pragma unroll
        for (int it = 0; it < 2; it++) {
            int m = xm + 32 * it;
            CP_ASYNC16(xd + (uint32_t)(m * XS_STRIDE + xq * 4) * 4,
                       X + (size_t)(row0 + m) * IN_F + xq * 4);
            int k = wk + 16 * it;
            CP_ASYNC16(wd + (uint32_t)(k * WS_STRIDE + wn4 * 4) * 4,
                       W + (size_t)k * HOF + col0 + wn4 * 4);
        }
        CP_COMMIT();
    }

    float acc[2][2][4];
#pragma unroll
    for (int a = 0; a < 2; a++)
#pragma unroll
        for (int b = 0; b < 2; b++)
#pragma unroll
            for (int c = 0; c < 4; c++) acc[a][b][c] = 0.0f;

    for (int kk = 0; kk < 8; kk++) {
        const int s = kk & 1;
        if (kk + 1 < 8) {
            const int k0 = (kk + 1) * 32;
            const uint32_t xd = sb + (uint32_t)(((kk + 1) & 1) * XS_STAGE) * 4;
            const uint32_t wd = sb + (uint32_t)(2 * XS_STAGE + ((kk + 1) & 1) * WS_STAGE) * 4;
#pragma unroll
            for (int it = 0; it < 2; it++) {
                int m = xm + 32 * it;
                CP_ASYNC16(xd + (uint32_t)(m * XS_STRIDE + xq * 4) * 4,
                           X + (size_t)(row0 + m) * IN_F + k0 + xq * 4);
                int k = wk + 16 * it;
                CP_ASYNC16(wd + (uint32_t)(k * WS_STRIDE + wn4 * 4) * 4,
                           W + (size_t)(k0 + k) * HOF + col0 + wn4 * 4);
            }
        }
        CP_COMMIT();
        CP_WAIT1();
        __syncthreads();

        const float* XS = SM + s * XS_STAGE;
        const float* WS = SM + 2 * XS_STAGE + s * WS_STAGE;
#pragma unroll
        for (int ks = 0; ks < 4; ks++) {
            const int kb = ks * 8;
            uint32_t bfr[2][2];
#pragma unroll
            for (int nt = 0; nt < 2; nt++) {
                int n = ncol0 + nt * 8 + g;
                bfr[nt][0] = __float_as_uint(to_tf32(WS[(kb + t) * WS_STRIDE + n]));
                bfr[nt][1] = __float_as_uint(to_tf32(WS[(kb + t + 4) * WS_STRIDE + n]));
            }
#pragma unroll
            for (int mt = 0; mt < 2; mt++) {
                int r0 = mrow0 + mt * 16;
                uint32_t afr[4];
                afr[0] = __float_as_uint(to_tf32(XS[(r0 + g) * XS_STRIDE + kb + t]));
                afr[1] = __float_as_uint(to_tf32(XS[(r0 + g + 8) * XS_STRIDE + kb + t]));
                afr[2] = __float_as_uint(to_tf32(XS[(r0 + g) * XS_STRIDE + kb + t + 4]));
                afr[3] = __float_as_uint(to_tf32(XS[(r0 + g + 8) * XS_STRIDE + kb + t + 4]));
#pragma unroll
                for (int nt = 0; nt < 2; nt++) mma_tf32(acc[mt][nt], afr, bfr[nt]);
            }
        }
        __syncthreads();
    }

    float* TS = SM;
#pragma unroll
    for (int mt = 0; mt < 2; mt++) {
        const int ja = mrow0 + mt * 16 + g;
        const int jb = ja + 8;
#pragma unroll
        for (int nt = 0; nt < 2; nt++) {
            const int cl = ncol0 + nt * 8 + 2 * t;
            TS[cl * TSW + ja] = acc[mt][nt][0];
            TS[(cl + 1) * TSW + ja] = acc[mt][nt][1];
            TS[cl * TSW + jb] = acc[mt][nt][2];
            TS[(cl + 1) * TSW + jb] = acc[mt][nt][3];
        }
    }
    __syncthreads();

#pragma unroll
    for (int r = 0; r < 8; r++) {
        const int j = wid * 8 + r;
#pragma unroll
        for (int it = 0; it < 2; it++) {
            const int cl = it * 32 + lane;
            g_h[(size_t)(row0 + j) * HOF + col0 + cl] = TS[cl * TSW + j];
        }
    }
    {
        const int hd = col0 >> 7;
        const int f0 = col0 & 127;
        const int p = lane;
        const int pos = (p & ~7) | kperm(p & 7);
#pragma unroll
        for (int r = 0; r < 8; r++) {
            const int cl = wid * 8 + r;
            uint32_t* dst = g_hTb + ((size_t)hd * OF + f0 + cl) * (N / 2) + row0 / 2;
            float lo = TS[cl * TSW + 2 * p];
            float hi = TS[cl * TSW + 2 * p + 1];
            dst[pos] = pack_bf16x2(hi, lo);
        }
    }
}

// ---------------------------------------------------------------------------
// Kernel B: ci / cj coefficients (head-major outputs). One warp per (n,h).
// ---------------------------------------------------------------------------
__global__ __launch_bounds__(128) void k_coeff(const float* __restrict__ a_i,
                                               const float* __restrict__ a_j) {
    const int n = blockIdx.x;
    const int h = threadIdx.x >> 5;
    const int lane = threadIdx.x & 31;

    float4 hv = *(const float4*)&g_h[n * HOF + h * OF + lane * 4];
    float4 ai = *(const float4*)&a_i[h * OF + lane * 4];
    float4 aj = *(const float4*)&a_j[h * OF + lane * 4];
    float si = hv.x * ai.x + hv.y * ai.y + hv.z * ai.z + hv.w * ai.w;
    float sj = hv.x * aj.x + hv.y * aj.y + hv.z * aj.z + hv.w * aj.w;
#pragma unroll
    for (int o = 16; o > 0; o >>= 1) {
        si += __shfl_down_sync(0xffffffffu, si, o);
        sj += __shfl_down_sync(0xffffffffu, sj, o);
    }
    if (lane == 0) {
        g_cih[h * N + n] = si;
        g_cjh[h * N + n] = sj;
    }
}

// ---------------------------------------------------------------------------
// Kernel D (bf16 m16n8k16, BM=32): grid 512 CTAs -> single wave, 3-4 CTAs/SM.
// 8 warps all share the 32 M-rows; warp tile 32x16 (N split).
// Per chunk: prefetch adj/cj(i+1) regs -> P(i) -> wait H(i) -> bar ->
//            issue H(i+1) -> mma(i).
// ---------------------------------------------------------------------------
#define D_BM 32
#define D_BK 32
#define NCHUNK (N / D_BK)
#define LDW 24                           // uint32 stride (16 used + 8 pad)

#define OFF_CI   0
#define OFF_BIAS 64
#define OFF_Z    192
#define OFF_H    256                     // 2 stages x 128x24 u32 = 2x3072
#define OFF_P    (OFF_H + 2*3072)        // 2 stages x 32x24 u32  = 2x768
#define SM_WORDS (OFF_P + 2*768)
#define SM_BYTES (SM_WORDS * 4)

__global__ __launch_bounds__(256, 4) void k_out_tc(const float* __restrict__ adj,
                                                   const float* __restrict__ bias,
                                                   float* __restrict__ out) {
    extern __shared__ float smf[];
    uint32_t* smu = (uint32_t*)smf;
    const uint32_t sb = smem_u32(smf);
    const int tid = threadIdx.x;
    const int wid = tid >> 5;
    const int lane = tid & 31;
    const int g = lane >> 2;
    const int t = lane & 3;
    const int i0 = blockIdx.x * D_BM;
    const int head = blockIdx.y;
    const int n0w = wid * 16;             // warp N base (8 warps x 16 cols)

    if (tid < 32) smf[OFF_CI + tid] = g_cih[head * N + i0 + tid];
    if (tid >= 64 && tid < 192) smf[OFF_BIAS + tid - 64] = bias[head * OF + tid - 64];

    // prologue: H(0) -> stage 0  (8KB: 512 cp.async16, 2/thread)
    {
        const uint32_t h_dst = sb + (OFF_H) * 4;
#pragma unroll
        for (int it = 0; it < 2; it++) {
            int idx = tid + 256 * it;
            int f = idx >> 2, q = idx & 3;
            CP_ASYNC16(h_dst + (uint32_t)(f * LDW + q * 4) * 4,
                       g_hTb + ((size_t)head * OF + f) * (N / 2) + q * 4);
        }
        CP_COMMIT();
    }

    // P-producer: 16 threads/row group; 2 row-iterations cover 32 rows
    const int prow = tid >> 4;            // 0..15
    const int jp = tid & 15;              // pair within chunk
    const int pcol = ((jp >> 3) << 3) | kperm(jp & 7);

    float2 aval[2];
#pragma unroll
    for (int it = 0; it < 2; it++)
        aval[it] = *(const float2*)&adj[(size_t)(i0 + prow + 16 * it) * N + 2 * jp];
    float2 cjv = *(const float2*)&g_cjh[head * N + 2 * jp];

    __syncthreads();

    float acc[2][2][4];
#pragma unroll
    for (int a = 0; a < 2; a++)
#pragma unroll
        for (int b = 0; b < 2; b++)
#pragma unroll
            for (int c = 0; c < 4; c++) acc[a][b][c] = 0.0f;
    float zacc[2] = {0.0f, 0.0f};

    const float* ci_s = smf + OFF_CI;

    for (int i = 0; i < NCHUNK; i++) {
        const int s = i & 1;
        const int j0 = i * D_BK;

        // prefetch adj/cj for chunk i+1
        float2 anx[2];
        float2 cjn = make_float2(0.f, 0.f);
        if (i + 1 < NCHUNK) {
#pragma unroll
            for (int it = 0; it < 2; it++)
                anx[it] = *(const float2*)&adj[(size_t)(i0 + prow + 16 * it) * N +
                                               j0 + D_BK + 2 * jp];
            cjn = *(const float2*)&g_cjh[head * N + j0 + D_BK + 2 * jp];
        }

        // P(i) into stage s
        uint32_t* PS = smu + OFF_P + s * 768;
#pragma unroll
        for (int it = 0; it < 2; it++) {
            const int r = prow + 16 * it;
            const float civ = ci_s[r];
            float s0 = civ + cjv.x;
            float s1 = civ + cjv.y;
            s0 = fmaxf(s0, SLOPE * s0) * aval[it].x;
            s1 = fmaxf(s1, SLOPE * s1) * aval[it].y;
            float e0 = __expf(s0);
            float e1 = __expf(s1);
            zacc[it] += e0 + e1;
            PS[r * LDW + pcol] = pack_bf16x2(e1 * aval[it].y, e0 * aval[it].x);
        }
#pragma unroll
        for (int it = 0; it < 2; it++) aval[it] = anx[it];
        cjv = cjn;

        CP_WAIT0();       // pending = {H(i)} exactly
        __syncthreads();  // P(i)+H(i) visible; mma(i-1) done everywhere

        // issue H(i+1) into stage s^1 (its readers were mma(i-1))
        if (i + 1 < NCHUNK) {
            const uint32_t h_dst = sb + (uint32_t)(OFF_H + (s ^ 1) * 3072) * 4;
            const int jp1 = (j0 + D_BK) / 2;
#pragma unroll
            for (int it = 0; it < 2; it++) {
                int idx = tid + 256 * it;
                int f = idx >> 2, q = idx & 3;
                CP_ASYNC16(h_dst + (uint32_t)(f * LDW + q * 4) * 4,
                           g_hTb + ((size_t)head * OF + f) * (N / 2) + jp1 + q * 4);
            }
            CP_COMMIT();
        }

        // mma(i): 2 k-steps of 16; all warps share the 32 A-rows (broadcast LDS)
        const uint32_t* HS = smu + OFF_H + s * 3072;
        uint32_t* PSb = smu + OFF_P + s * 768;
#pragma unroll
        for (int ks = 0; ks < 2; ks++) {
            const int kc = ks * 8 + 2 * t;
            uint32_t bfr[2][2];
#pragma unroll
            for (int nt = 0; nt < 2; nt++) {
                int n = n0w + nt * 8 + g;
                *(uint2*)bfr[nt] = *(const uint2*)&HS[n * LDW + kc];
            }
#pragma unroll
            for (int mt = 0; mt < 2; mt++) {
                int r0 = mt * 16;
                uint2 a0 = *(const uint2*)&PSb[(r0 + g) * LDW + kc];
                uint2 a1 = *(const uint2*)&PSb[(r0 + g + 8) * LDW + kc];
                uint32_t afr[4] = {a0.x, a1.x, a0.y, a1.y};
#pragma unroll
                for (int nt = 0; nt < 2; nt++) mma_bf16(acc[mt][nt], afr, bfr[nt]);
            }
        }
    }

    // z reduce: 16 lanes (jp) share a row; xor-reduce within 16-lane halves
#pragma unroll
    for (int it = 0; it < 2; it++) {
        float v = zacc[it];
#pragma unroll
        for (int o = 8; o > 0; o >>= 1) v += __shfl_xor_sync(0xffffffffu, v, o);
        if ((lane & 15) == 0) smf[OFF_Z + prow + 16 * it] = v;
    }
    __syncthreads();

    // epilogue: scale by 1/z, add bias
    const float* biasS = smf + OFF_BIAS;
    const float* zS = smf + OFF_Z;
#pragma unroll
    for (int mt = 0; mt < 2; mt++) {
        const int r = mt * 16 + g;
        const int ra = i0 + r;
        const float za = 1.0f / zS[r];
        const float zb = 1.0f / zS[r + 8];
#pragma unroll
        for (int nt = 0; nt < 2; nt++) {
            const int col = n0w + nt * 8 + 2 * t;
            float2 v0, v1;
            v0.x = acc[mt][nt][0] * za + biasS[col];
            v0.y = acc[mt][nt][1] * za + biasS[col + 1];
            v1.x = acc[mt][nt][2] * zb + biasS[col];
            v1.y = acc[mt][nt][3] * zb + biasS[col + 1];
            *(float2*)&out[(size_t)ra * HOF + head * OF + col] = v0;
            *(float2*)&out[(size_t)(ra + 8) * HOF + head * OF + col] = v1;
        }
    }
}

// ---------------------------------------------------------------------------
extern "C" void kernel_launch(void* const* d_in, const int* in_sizes, int n_in,
                              void* d_out, int out_size) {
    const float* x    = (const float*)d_in[0];   // (4096, 256)
    const float* adj  = (const float*)d_in[1];   // (4096, 4096)
    const float* W    = (const float*)d_in[2];   // (256, 512)
    const float* a_i  = (const float*)d_in[3];   // (4, 128, 1)
    const float* a_j  = (const float*)d_in[4];   // (4, 128, 1)
    const float* bias = (const float*)d_in[5];   // (512,)
    float* out = (float*)d_out;                  // (4096, 512)

    cudaFuncSetAttribute(k_out_tc, cudaFuncAttributeMaxDynamicSharedMemorySize, SM_BYTES);

    dim3 gA(HOF / 64, N / 64);
    k_gemm_h<<<gA, 256>>>(x, W);
    k_coeff<<<N, 128>>>(a_i, a_j);
    dim3 gD(N / D_BM, HH);
    k_out_tc<<<gD, 256, SM_BYTES>>>(adj, bias, out);
}